// round 13
// baseline (speedup 1.0000x reference)
#include <cuda_runtime.h>
#include <cuda_bf16.h>
#include <cuda_fp16.h>

#define NN 131072      // nodes
#define NE 2097152     // edges
#define F_IN 32
#define HID 64
#define G_FEAT 16
#define NG 1024        // graphs
#define BN_EPS 1e-5f
#define NSLOT 256      // BN partial slots

// ---------------- scratch ------------------------------------------------------
__device__ int     g_deg[NN];
__device__ int     g_start[NN];
__device__ int     g_ptr[NN];
__device__ int     g_esrc[NE];
__device__ int     g_ecnt;
__device__ float   g_dinv[NN];
__device__ __half2 g_xwh[NN * 32];           // xw' fp16 payload
__device__ float4  g_agg[NN * 16];           // layer-1 v (fp32, gemm2 input)
__device__ __half2 g_aggh[NN * 32];          // layer-2 v (fp16, pool input)
__device__ float g_psum1[NSLOT * HID], g_pss1[NSLOT * HID];
__device__ float g_psum2[NSLOT * HID], g_pss2[NSLOT * HID];
__device__ float g_scale1[HID], g_shift1[HID];
__device__ float g_scale2[HID], g_shift2[HID];
__device__ float g_pool[NG * HID];
__device__ float g_cnt[NG];

// ---------------- helpers -----------------------------------------------------
__device__ __forceinline__ void red_add_v4(float* addr, float4 v) {
    asm volatile("red.global.add.v4.f32 [%0], {%1, %2, %3, %4};"
                 :: "l"(addr), "f"(v.x), "f"(v.y), "f"(v.z), "f"(v.w)
                 : "memory");
}
__device__ __forceinline__ void red_add_v2(float* addr, float2 v) {
    asm volatile("red.global.add.v2.f32 [%0], {%1, %2};"
                 :: "l"(addr), "f"(v.x), "f"(v.y)
                 : "memory");
}
__device__ __forceinline__ unsigned h2_as_u(__half2 h) {
    return *reinterpret_cast<unsigned*>(&h);
}

// ---------------- CSR build -----------------------------------------------------
__global__ void k_degree(const int* __restrict__ dst) {
    int e = blockIdx.x * blockDim.x + threadIdx.x;
    atomicAdd(&g_deg[dst[e]], 1);
}

__global__ void k_offsets() {
    int i = blockIdx.x * blockDim.x + threadIdx.x;
    int lane = threadIdx.x & 31;
    int d = g_deg[i];
    int incl = d;
#pragma unroll
    for (int off = 1; off < 32; off <<= 1) {
        int t = __shfl_up_sync(0xffffffffu, incl, off);
        if (lane >= off) incl += t;
    }
    int total = __shfl_sync(0xffffffffu, incl, 31);
    int base = 0;
    if (lane == 31) base = atomicAdd(&g_ecnt, total);
    base = __shfl_sync(0xffffffffu, base, 31);
    int st = base + incl - d;
    g_start[i] = st;
    g_ptr[i]   = st;
    g_dinv[i]  = rsqrtf((float)d + 1.0f);
}

__global__ void k_fill(const int* __restrict__ src, const int* __restrict__ dst) {
    int e = blockIdx.x * blockDim.x + threadIdx.x;
    int d = __ldg(dst + e);
    int p = atomicAdd(&g_ptr[d], 1);
    g_esrc[p] = __ldg(src + e);
}

// ---------------- compute kernels ----------------------------------------------

// tiled: xw' = (x @ W1) * dinv -> fp16. 64 nodes x 64 cols per block, 4x4 micro.
__global__ void k_gemm1(const float* __restrict__ x, const float* __restrict__ W) {
    __shared__ float xs[64 * 33];     // [node][k] padded
    __shared__ float ws[F_IN * 64];   // [k][col]
    int tid = threadIdx.x;

    for (int i = tid; i < F_IN * 64; i += 256) ws[i] = W[i];
    const float4* xp = (const float4*)x + (size_t)blockIdx.x * 512;
#pragma unroll
    for (int it = 0; it < 2; it++) {
        int i = tid + it * 256;            // 0..511 float4 of tile
        int node = i >> 3, q = i & 7;      // 8 float4 per node row
        float4 a = xp[i];
        float* hp = &xs[node * 33];
        hp[4 * q + 0] = a.x; hp[4 * q + 1] = a.y;
        hp[4 * q + 2] = a.z; hp[4 * q + 3] = a.w;
    }
    __syncthreads();

    int tx = tid & 15, ty = tid >> 4;
    float acc[4][4] = {};
#pragma unroll
    for (int k = 0; k < F_IN; k++) {
        float4 wv = *(const float4*)&ws[k * 64 + 4 * tx];
        float h0 = xs[(4 * ty + 0) * 33 + k];
        float h1 = xs[(4 * ty + 1) * 33 + k];
        float h2 = xs[(4 * ty + 2) * 33 + k];
        float h3 = xs[(4 * ty + 3) * 33 + k];
        acc[0][0] += h0 * wv.x; acc[0][1] += h0 * wv.y; acc[0][2] += h0 * wv.z; acc[0][3] += h0 * wv.w;
        acc[1][0] += h1 * wv.x; acc[1][1] += h1 * wv.y; acc[1][2] += h1 * wv.z; acc[1][3] += h1 * wv.w;
        acc[2][0] += h2 * wv.x; acc[2][1] += h2 * wv.y; acc[2][2] += h2 * wv.z; acc[2][3] += h2 * wv.w;
        acc[3][0] += h3 * wv.x; acc[3][1] += h3 * wv.y; acc[3][2] += h3 * wv.z; acc[3][3] += h3 * wv.w;
    }

    int node0 = blockIdx.x * 64 + 4 * ty;
#pragma unroll
    for (int i = 0; i < 4; i++) {
        float di = g_dinv[node0 + i];
        __half2 h0 = __floats2half2_rn(acc[i][0] * di, acc[i][1] * di);
        __half2 h1 = __floats2half2_rn(acc[i][2] * di, acc[i][3] * di);
        ((uint2*)&g_xwh[(size_t)(node0 + i) * 32])[tx] = make_uint2(h2_as_u(h0), h2_as_u(h1));
    }
}

// gather: one warp per node, fp16 payload, fp32 accumulate.
template<bool FP16OUT>
__global__ void k_gather(const float* __restrict__ bias,
                         float* __restrict__ psum, float* __restrict__ pss) {
    __shared__ int    sidx[8][32];
    __shared__ float2 ssum[8][32];
    __shared__ float2 ssq[8][32];
    int tid = threadIdx.x;
    int warp = tid >> 5, lane = tid & 31;
    int node = blockIdx.x * 8 + warp;

    int st = g_start[node];
    int dg = g_deg[node];
    const int* ep = &g_esrc[st];
    const __half2* XW = g_xwh;

    float2 acc = __half22float2(XW[(size_t)node * 32 + lane]);   // self loop

    for (int k0 = 0; k0 < dg; k0 += 32) {
        int nb = dg - k0; if (nb > 32) nb = 32;
        int my = (lane < nb) ? __ldg(ep + k0 + lane) : 0;
        sidx[warp][lane] = my;
        __syncwarp();
        int e = 0;
        for (; e + 4 <= nb; e += 4) {
            int s0 = sidx[warp][e + 0];
            int s1 = sidx[warp][e + 1];
            int s2 = sidx[warp][e + 2];
            int s3 = sidx[warp][e + 3];
            float2 v0 = __half22float2(__ldg(&XW[(size_t)s0 * 32 + lane]));
            float2 v1 = __half22float2(__ldg(&XW[(size_t)s1 * 32 + lane]));
            float2 v2 = __half22float2(__ldg(&XW[(size_t)s2 * 32 + lane]));
            float2 v3 = __half22float2(__ldg(&XW[(size_t)s3 * 32 + lane]));
            acc.x += v0.x + v1.x + v2.x + v3.x;
            acc.y += v0.y + v1.y + v2.y + v3.y;
        }
        for (; e < nb; e++) {
            int s0 = sidx[warp][e];
            float2 v0 = __half22float2(__ldg(&XW[(size_t)s0 * 32 + lane]));
            acc.x += v0.x; acc.y += v0.y;
        }
        __syncwarp();
    }

    float di = g_dinv[node];
    float2 b2 = ((const float2*)bias)[lane];
    float2 v = make_float2(acc.x * di + b2.x, acc.y * di + b2.y);
    if (FP16OUT) {
        g_aggh[(size_t)node * 32 + lane] = __floats2half2_rn(v.x, v.y);
    } else {
        ((float2*)g_agg)[(size_t)node * 32 + lane] = v;
    }

    ssum[warp][lane] = v;
    ssq[warp][lane]  = make_float2(v.x * v.x, v.y * v.y);
    __syncthreads();
    if (warp == 0) {
        float2 s = make_float2(0.f, 0.f), q = make_float2(0.f, 0.f);
#pragma unroll
        for (int r = 0; r < 8; r++) {
            float2 a = ssum[r][lane]; s.x += a.x; s.y += a.y;
            float2 b = ssq[r][lane];  q.x += b.x; q.y += b.y;
        }
        int slot = blockIdx.x & (NSLOT - 1);
        red_add_v2(&psum[slot * HID + 2 * lane], s);
        red_add_v2(&pss[slot * HID + 2 * lane], q);
    }
}

__global__ void k_bnstats(const float* __restrict__ psum, const float* __restrict__ pss,
                          const float* __restrict__ gamma, const float* __restrict__ beta,
                          float* __restrict__ scale, float* __restrict__ shift) {
    int f = threadIdx.x;
    float s = 0.f, q = 0.f;
#pragma unroll 8
    for (int r = 0; r < NSLOT; r++) {
        s += psum[r * HID + f];
        q += pss[r * HID + f];
    }
    const float invN = 1.0f / (float)NN;
    float mu = s * invN;
    float var = q * invN - mu * mu;
    float sc = gamma[f] * rsqrtf(var + BN_EPS);
    scale[f] = sc;
    shift[f] = beta[f] - mu * sc;
}

// tiled: h = relu(v1*sc+sh) ; xw2' = (h @ W2)*dinv -> fp16
__global__ void k_gemm2(const float* __restrict__ W) {
    __shared__ float hs[64 * 65];
    __shared__ float ws[64 * 64];
    __shared__ float sc[HID], sh[HID];
    int tid = threadIdx.x;

    if (tid < HID) { sc[tid] = g_scale1[tid]; sh[tid] = g_shift1[tid]; }
    for (int i = tid; i < 64 * 64; i += 256) ws[i] = W[i];
    __syncthreads();

    const float4* ag = (const float4*)g_agg + (size_t)blockIdx.x * 1024;
#pragma unroll
    for (int it = 0; it < 4; it++) {
        int i = tid + it * 256;
        int node = i >> 4, q = i & 15;
        float4 a = ag[i];
        float h0 = fmaxf(a.x * sc[4 * q + 0] + sh[4 * q + 0], 0.f);
        float h1 = fmaxf(a.y * sc[4 * q + 1] + sh[4 * q + 1], 0.f);
        float h2 = fmaxf(a.z * sc[4 * q + 2] + sh[4 * q + 2], 0.f);
        float h3 = fmaxf(a.w * sc[4 * q + 3] + sh[4 * q + 3], 0.f);
        float* hp = &hs[node * 65];
        hp[4 * q + 0] = h0; hp[4 * q + 1] = h1;
        hp[4 * q + 2] = h2; hp[4 * q + 3] = h3;
    }
    __syncthreads();

    int tx = tid & 15, ty = tid >> 4;
    float acc[4][4] = {};
#pragma unroll 16
    for (int k = 0; k < 64; k++) {
        float4 wv = *(const float4*)&ws[k * 64 + 4 * tx];
        float h0 = hs[(4 * ty + 0) * 65 + k];
        float h1 = hs[(4 * ty + 1) * 65 + k];
        float h2 = hs[(4 * ty + 2) * 65 + k];
        float h3 = hs[(4 * ty + 3) * 65 + k];
        acc[0][0] += h0 * wv.x; acc[0][1] += h0 * wv.y; acc[0][2] += h0 * wv.z; acc[0][3] += h0 * wv.w;
        acc[1][0] += h1 * wv.x; acc[1][1] += h1 * wv.y; acc[1][2] += h1 * wv.z; acc[1][3] += h1 * wv.w;
        acc[2][0] += h2 * wv.x; acc[2][1] += h2 * wv.y; acc[2][2] += h2 * wv.z; acc[2][3] += h2 * wv.w;
        acc[3][0] += h3 * wv.x; acc[3][1] += h3 * wv.y; acc[3][2] += h3 * wv.z; acc[3][3] += h3 * wv.w;
    }

    int node0 = blockIdx.x * 64 + 4 * ty;
#pragma unroll
    for (int i = 0; i < 4; i++) {
        float di = g_dinv[node0 + i];
        __half2 h0 = __floats2half2_rn(acc[i][0] * di, acc[i][1] * di);
        __half2 h1 = __floats2half2_rn(acc[i][2] * di, acc[i][3] * di);
        ((uint2*)&g_xwh[(size_t)(node0 + i) * 32])[tx] = make_uint2(h2_as_u(h0), h2_as_u(h1));
    }
}

// h2 = relu(v2*sc2+sh2) from fp16 v2 ; pool[batch[i]] += h2 ; cnt
__global__ void k_pool(const int* __restrict__ batch) {
    unsigned t = blockIdx.x * blockDim.x + threadIdx.x;
    unsigned i = t >> 4;
    unsigned j = t & 15u;
    int g = batch[i];
    uint2 u = ((const uint2*)g_aggh)[(size_t)i * 16 + j];
    __half2 a0 = *reinterpret_cast<__half2*>(&u.x);
    __half2 a1 = *reinterpret_cast<__half2*>(&u.y);
    float2 f0 = __half22float2(a0);
    float2 f1 = __half22float2(a1);
    float4 s4 = ((const float4*)g_scale2)[j];
    float4 h4 = ((const float4*)g_shift2)[j];
    float4 hh;
    hh.x = fmaxf(f0.x * s4.x + h4.x, 0.f);
    hh.y = fmaxf(f0.y * s4.y + h4.y, 0.f);
    hh.z = fmaxf(f1.x * s4.z + h4.z, 0.f);
    hh.w = fmaxf(f1.y * s4.w + h4.w, 0.f);
    red_add_v4(&g_pool[(size_t)g * HID + 4 * j], hh);
    if (j == 0) atomicAdd(&g_cnt[g], 1.0f);
}

__global__ void k_head(const float* __restrict__ gf,
                       const float* __restrict__ Wo1, const float* __restrict__ bo1,
                       const float* __restrict__ Wo2, const float* __restrict__ bo2,
                       const float* __restrict__ Wb1, const float* __restrict__ bb1,
                       const float* __restrict__ Wb2, const float* __restrict__ bb2,
                       float* __restrict__ out) {
    int g = blockIdx.x;
    int lane = threadIdx.x;
    __shared__ float c[HID + G_FEAT];
    float inv = 1.0f / fmaxf(g_cnt[g], 1.0f);
    for (int k = lane; k < HID; k += 32) c[k] = g_pool[(size_t)g * HID + k] * inv;
    if (lane < G_FEAT) c[HID + lane] = gf[(size_t)g * G_FEAT + lane];
    __syncwarp();

    float ho = bo1[lane];
#pragma unroll 8
    for (int k = 0; k < HID + G_FEAT; k++) ho += c[k] * Wo1[k * 32 + lane];
    ho = fmaxf(ho, 0.f) * Wo2[lane];
#pragma unroll
    for (int o = 16; o; o >>= 1) ho += __shfl_xor_sync(0xffffffffu, ho, o);
    if (lane == 0) out[g] = ho + bo2[0];

    float hb = bb1[lane];
#pragma unroll 8
    for (int k = 0; k < HID + G_FEAT; k++) hb += c[k] * Wb1[k * 32 + lane];
    hb = fmaxf(hb, 0.f) * Wb2[lane];
#pragma unroll
    for (int o = 16; o; o >>= 1) hb += __shfl_xor_sync(0xffffffffu, hb, o);
    if (lane == 0) out[NG + g] = hb + bb2[0];
}

// ---------------- launch --------------------------------------------------------
extern "C" void kernel_launch(void* const* d_in, const int* in_sizes, int n_in,
                              void* d_out, int out_size) {
    const float* x      = (const float*)d_in[0];
    const int*   ei     = (const int*)d_in[1];
    const int*   batch  = (const int*)d_in[2];
    const float* gf     = (const float*)d_in[3];
    const float* W1     = (const float*)d_in[4];
    const float* b1     = (const float*)d_in[5];
    const float* gamma1 = (const float*)d_in[6];
    const float* beta1  = (const float*)d_in[7];
    const float* W2     = (const float*)d_in[8];
    const float* b2     = (const float*)d_in[9];
    const float* gamma2 = (const float*)d_in[10];
    const float* beta2  = (const float*)d_in[11];
    const float* Wo1    = (const float*)d_in[12];
    const float* bo1    = (const float*)d_in[13];
    const float* Wo2    = (const float*)d_in[14];
    const float* bo2    = (const float*)d_in[15];
    const float* Wb1    = (const float*)d_in[16];
    const float* bb1    = (const float*)d_in[17];
    const float* Wb2    = (const float*)d_in[18];
    const float* bb2    = (const float*)d_in[19];
    float* out = (float*)d_out;

    const int* src = ei;
    const int* dst = ei + NE;

    void *p_deg, *p_ecnt, *p_ps1, *p_pq1, *p_ps2, *p_pq2, *p_pool, *p_cnt;
    void *p_scale1, *p_shift1, *p_scale2, *p_shift2;
    cudaGetSymbolAddress(&p_deg,  g_deg);
    cudaGetSymbolAddress(&p_ecnt, g_ecnt);
    cudaGetSymbolAddress(&p_ps1,  g_psum1);
    cudaGetSymbolAddress(&p_pq1,  g_pss1);
    cudaGetSymbolAddress(&p_ps2,  g_psum2);
    cudaGetSymbolAddress(&p_pq2,  g_pss2);
    cudaGetSymbolAddress(&p_pool, g_pool);
    cudaGetSymbolAddress(&p_cnt,  g_cnt);
    cudaGetSymbolAddress(&p_scale1, g_scale1);
    cudaGetSymbolAddress(&p_shift1, g_shift1);
    cudaGetSymbolAddress(&p_scale2, g_scale2);
    cudaGetSymbolAddress(&p_shift2, g_shift2);

    // persistent side streams/events (created once, outside capture)
    static cudaStream_t s_mem = nullptr, s_fill = nullptr;
    static cudaEvent_t  e_root = nullptr, e_mem = nullptr, e_off = nullptr, e_fill = nullptr;
    if (!s_mem) {
        cudaStreamCreateWithFlags(&s_mem,  cudaStreamNonBlocking);
        cudaStreamCreateWithFlags(&s_fill, cudaStreamNonBlocking);
        cudaEventCreateWithFlags(&e_root, cudaEventDisableTiming);
        cudaEventCreateWithFlags(&e_mem,  cudaEventDisableTiming);
        cudaEventCreateWithFlags(&e_off,  cudaEventDisableTiming);
        cudaEventCreateWithFlags(&e_fill, cudaEventDisableTiming);
    }
    cudaStream_t m = 0;   // main (capture) stream

    // fork: BN/pool memsets on side stream
    cudaEventRecord(e_root, m);
    cudaStreamWaitEvent(s_mem, e_root, 0);
    cudaMemsetAsync(p_ps1,  0, sizeof(float) * NSLOT * HID, s_mem);
    cudaMemsetAsync(p_pq1,  0, sizeof(float) * NSLOT * HID, s_mem);
    cudaMemsetAsync(p_ps2,  0, sizeof(float) * NSLOT * HID, s_mem);
    cudaMemsetAsync(p_pq2,  0, sizeof(float) * NSLOT * HID, s_mem);
    cudaMemsetAsync(p_pool, 0, sizeof(float) * NG * HID, s_mem);
    cudaMemsetAsync(p_cnt,  0, sizeof(float) * NG, s_mem);
    cudaEventRecord(e_mem, s_mem);

    // main: degree chain
    cudaMemsetAsync(p_deg,  0, sizeof(int) * NN, m);
    cudaMemsetAsync(p_ecnt, 0, sizeof(int), m);
    k_degree<<<NE / 256, 256, 0, m>>>(dst);
    k_offsets<<<NN / 256, 256, 0, m>>>();
    cudaEventRecord(e_off, m);

    // fork: CSR fill in parallel with gemm1
    cudaStreamWaitEvent(s_fill, e_off, 0);
    k_fill<<<NE / 256, 256, 0, s_fill>>>(src, dst);
    cudaEventRecord(e_fill, s_fill);

    k_gemm1<<<NN / 64, 256, 0, m>>>(x, W1);

    // join before gather
    cudaStreamWaitEvent(m, e_fill, 0);
    cudaStreamWaitEvent(m, e_mem, 0);

    // ----- layer 1 -----
    k_gather<false><<<NN / 8, 256, 0, m>>>(b1, (float*)p_ps1, (float*)p_pq1);
    k_bnstats<<<1, HID, 0, m>>>((const float*)p_ps1, (const float*)p_pq1, gamma1, beta1,
                                (float*)p_scale1, (float*)p_shift1);

    // ----- layer 2 -----
    k_gemm2<<<NN / 64, 256, 0, m>>>(W2);
    k_gather<true><<<NN / 8, 256, 0, m>>>(b2, (float*)p_ps2, (float*)p_pq2);
    k_bnstats<<<1, HID, 0, m>>>((const float*)p_ps2, (const float*)p_pq2, gamma2, beta2,
                                (float*)p_scale2, (float*)p_shift2);

    // ----- pool + heads -----
    k_pool<<<(NN * 16) / 256, 256, 0, m>>>(batch);
    k_head<<<NG, 32, 0, m>>>(gf, Wo1, bo1, Wo2, bo2, Wb1, bb1, Wb2, bb2, out);
}

// round 17
// speedup vs baseline: 1.2894x; 1.2894x over previous
#include <cuda_runtime.h>
#include <cuda_bf16.h>
#include <cuda_fp16.h>

#define NN 131072      // nodes
#define NE 2097152     // edges
#define F_IN 32
#define HID 64
#define G_FEAT 16
#define NG 1024        // graphs
#define BN_EPS 1e-5f
#define NSLOT 256      // BN partial slots

// ---------------- scratch ------------------------------------------------------
__device__ int     g_deg[NN];
__device__ int     g_start[NN];
__device__ int     g_ptr[NN];
__device__ int     g_esrc[NE];
__device__ int     g_ecnt;
__device__ float   g_dinv[NN];
__device__ __half2 g_xwh[NN * 32];           // xw' fp16 payload
__device__ float4  g_agg[NN * 16];           // layer-1 v (fp32, gemm2 input)
__device__ __half2 g_aggh[NN * 32];          // layer-2 v (fp16, pool input)
__device__ float g_psum1[NSLOT * HID], g_pss1[NSLOT * HID];
__device__ float g_psum2[NSLOT * HID], g_pss2[NSLOT * HID];
__device__ float g_scale1[HID], g_shift1[HID];
__device__ float g_scale2[HID], g_shift2[HID];
__device__ float g_pool[NG * HID];
__device__ float g_cnt[NG];

// ---------------- helpers -----------------------------------------------------
__device__ __forceinline__ void red_add_v4(float* addr, float4 v) {
    asm volatile("red.global.add.v4.f32 [%0], {%1, %2, %3, %4};"
                 :: "l"(addr), "f"(v.x), "f"(v.y), "f"(v.z), "f"(v.w)
                 : "memory");
}
__device__ __forceinline__ void red_add_v2(float* addr, float2 v) {
    asm volatile("red.global.add.v2.f32 [%0], {%1, %2};"
                 :: "l"(addr), "f"(v.x), "f"(v.y)
                 : "memory");
}
__device__ __forceinline__ unsigned h2_as_u(__half2 h) {
    return *reinterpret_cast<unsigned*>(&h);
}

// ---------------- CSR build -----------------------------------------------------
__global__ void k_degree(const int* __restrict__ dst) {
    int e = blockIdx.x * blockDim.x + threadIdx.x;
    atomicAdd(&g_deg[dst[e]], 1);
}

__global__ void k_offsets() {
    int i = blockIdx.x * blockDim.x + threadIdx.x;
    int lane = threadIdx.x & 31;
    int d = g_deg[i];
    int incl = d;
#pragma unroll
    for (int off = 1; off < 32; off <<= 1) {
        int t = __shfl_up_sync(0xffffffffu, incl, off);
        if (lane >= off) incl += t;
    }
    int total = __shfl_sync(0xffffffffu, incl, 31);
    int base = 0;
    if (lane == 31) base = atomicAdd(&g_ecnt, total);
    base = __shfl_sync(0xffffffffu, base, 31);
    int st = base + incl - d;
    g_start[i] = st;
    g_ptr[i]   = st;
    g_dinv[i]  = rsqrtf((float)d + 1.0f);
}

__global__ void k_fill(const int* __restrict__ src, const int* __restrict__ dst) {
    int e = blockIdx.x * blockDim.x + threadIdx.x;
    int d = __ldg(dst + e);
    int p = atomicAdd(&g_ptr[d], 1);
    g_esrc[p] = __ldg(src + e);
}

// ---------------- compute kernels ----------------------------------------------

// tiled: xw' = (x @ W1) * dinv -> fp16. 64 nodes x 64 cols per block, 4x4 micro.
__global__ void k_gemm1(const float* __restrict__ x, const float* __restrict__ W) {
    __shared__ float xs[64 * 33];     // [node][k] padded
    __shared__ float ws[F_IN * 64];   // [k][col]
    int tid = threadIdx.x;

    for (int i = tid; i < F_IN * 64; i += 256) ws[i] = W[i];
    const float4* xp = (const float4*)x + (size_t)blockIdx.x * 512;
#pragma unroll
    for (int it = 0; it < 2; it++) {
        int i = tid + it * 256;
        int node = i >> 3, q = i & 7;
        float4 a = xp[i];
        float* hp = &xs[node * 33];
        hp[4 * q + 0] = a.x; hp[4 * q + 1] = a.y;
        hp[4 * q + 2] = a.z; hp[4 * q + 3] = a.w;
    }
    __syncthreads();

    int tx = tid & 15, ty = tid >> 4;
    float acc[4][4] = {};
#pragma unroll
    for (int k = 0; k < F_IN; k++) {
        float4 wv = *(const float4*)&ws[k * 64 + 4 * tx];
        float h0 = xs[(4 * ty + 0) * 33 + k];
        float h1 = xs[(4 * ty + 1) * 33 + k];
        float h2 = xs[(4 * ty + 2) * 33 + k];
        float h3 = xs[(4 * ty + 3) * 33 + k];
        acc[0][0] += h0 * wv.x; acc[0][1] += h0 * wv.y; acc[0][2] += h0 * wv.z; acc[0][3] += h0 * wv.w;
        acc[1][0] += h1 * wv.x; acc[1][1] += h1 * wv.y; acc[1][2] += h1 * wv.z; acc[1][3] += h1 * wv.w;
        acc[2][0] += h2 * wv.x; acc[2][1] += h2 * wv.y; acc[2][2] += h2 * wv.z; acc[2][3] += h2 * wv.w;
        acc[3][0] += h3 * wv.x; acc[3][1] += h3 * wv.y; acc[3][2] += h3 * wv.z; acc[3][3] += h3 * wv.w;
    }

    int node0 = blockIdx.x * 64 + 4 * ty;
#pragma unroll
    for (int i = 0; i < 4; i++) {
        float di = g_dinv[node0 + i];
        __half2 h0 = __floats2half2_rn(acc[i][0] * di, acc[i][1] * di);
        __half2 h1 = __floats2half2_rn(acc[i][2] * di, acc[i][3] * di);
        ((uint2*)&g_xwh[(size_t)(node0 + i) * 32])[tx] = make_uint2(h2_as_u(h0), h2_as_u(h1));
    }
}

// gather: one warp per node, fp16 payload, fp32 accumulate.
// indices broadcast via shfl (no smem stage), MLP=8 front-batched loads.
template<bool FP16OUT>
__global__ void k_gather(const float* __restrict__ bias,
                         float* __restrict__ psum, float* __restrict__ pss) {
    __shared__ float2 ssum[8][32];
    __shared__ float2 ssq[8][32];
    int tid = threadIdx.x;
    int warp = tid >> 5, lane = tid & 31;
    int node = blockIdx.x * 8 + warp;

    int st = g_start[node];
    int dg = g_deg[node];
    const int* ep = &g_esrc[st];
    const __half2* XW = g_xwh;

    float2 acc = __half22float2(XW[(size_t)node * 32 + lane]);   // self loop

    for (int k0 = 0; k0 < dg; k0 += 32) {
        int nb = dg - k0; if (nb > 32) nb = 32;
        int my = (lane < nb) ? __ldg(ep + k0 + lane) : 0;
        int e = 0;
        for (; e + 8 <= nb; e += 8) {
            int s0 = __shfl_sync(0xffffffffu, my, e + 0);
            int s1 = __shfl_sync(0xffffffffu, my, e + 1);
            int s2 = __shfl_sync(0xffffffffu, my, e + 2);
            int s3 = __shfl_sync(0xffffffffu, my, e + 3);
            int s4 = __shfl_sync(0xffffffffu, my, e + 4);
            int s5 = __shfl_sync(0xffffffffu, my, e + 5);
            int s6 = __shfl_sync(0xffffffffu, my, e + 6);
            int s7 = __shfl_sync(0xffffffffu, my, e + 7);
            __half2 h0 = __ldg(&XW[(size_t)s0 * 32 + lane]);
            __half2 h1 = __ldg(&XW[(size_t)s1 * 32 + lane]);
            __half2 h2 = __ldg(&XW[(size_t)s2 * 32 + lane]);
            __half2 h3 = __ldg(&XW[(size_t)s3 * 32 + lane]);
            __half2 h4 = __ldg(&XW[(size_t)s4 * 32 + lane]);
            __half2 h5 = __ldg(&XW[(size_t)s5 * 32 + lane]);
            __half2 h6 = __ldg(&XW[(size_t)s6 * 32 + lane]);
            __half2 h7 = __ldg(&XW[(size_t)s7 * 32 + lane]);
            float2 v0 = __half22float2(h0), v1 = __half22float2(h1);
            float2 v2 = __half22float2(h2), v3 = __half22float2(h3);
            float2 v4 = __half22float2(h4), v5 = __half22float2(h5);
            float2 v6 = __half22float2(h6), v7 = __half22float2(h7);
            acc.x += (v0.x + v1.x) + (v2.x + v3.x) + (v4.x + v5.x) + (v6.x + v7.x);
            acc.y += (v0.y + v1.y) + (v2.y + v3.y) + (v4.y + v5.y) + (v6.y + v7.y);
        }
        for (; e < nb; e++) {
            int s0 = __shfl_sync(0xffffffffu, my, e);
            float2 v0 = __half22float2(__ldg(&XW[(size_t)s0 * 32 + lane]));
            acc.x += v0.x; acc.y += v0.y;
        }
    }

    float di = g_dinv[node];
    float2 b2 = ((const float2*)bias)[lane];
    float2 v = make_float2(acc.x * di + b2.x, acc.y * di + b2.y);
    if (FP16OUT) {
        g_aggh[(size_t)node * 32 + lane] = __floats2half2_rn(v.x, v.y);
    } else {
        ((float2*)g_agg)[(size_t)node * 32 + lane] = v;
    }

    ssum[warp][lane] = v;
    ssq[warp][lane]  = make_float2(v.x * v.x, v.y * v.y);
    __syncthreads();
    if (warp == 0) {
        float2 s = make_float2(0.f, 0.f), q = make_float2(0.f, 0.f);
#pragma unroll
        for (int r = 0; r < 8; r++) {
            float2 a = ssum[r][lane]; s.x += a.x; s.y += a.y;
            float2 b = ssq[r][lane];  q.x += b.x; q.y += b.y;
        }
        int slot = blockIdx.x & (NSLOT - 1);
        red_add_v2(&psum[slot * HID + 2 * lane], s);
        red_add_v2(&pss[slot * HID + 2 * lane], q);
    }
}

__global__ void k_bnstats(const float* __restrict__ psum, const float* __restrict__ pss,
                          const float* __restrict__ gamma, const float* __restrict__ beta,
                          float* __restrict__ scale, float* __restrict__ shift) {
    int f = threadIdx.x;
    float s = 0.f, q = 0.f;
#pragma unroll 8
    for (int r = 0; r < NSLOT; r++) {
        s += psum[r * HID + f];
        q += pss[r * HID + f];
    }
    const float invN = 1.0f / (float)NN;
    float mu = s * invN;
    float var = q * invN - mu * mu;
    float sc = gamma[f] * rsqrtf(var + BN_EPS);
    scale[f] = sc;
    shift[f] = beta[f] - mu * sc;
}

// tiled: h = relu(v1*sc+sh) ; xw2' = (h @ W2)*dinv -> fp16
__global__ void k_gemm2(const float* __restrict__ W) {
    __shared__ float hs[64 * 65];
    __shared__ float ws[64 * 64];
    __shared__ float sc[HID], sh[HID];
    int tid = threadIdx.x;

    if (tid < HID) { sc[tid] = g_scale1[tid]; sh[tid] = g_shift1[tid]; }
    for (int i = tid; i < 64 * 64; i += 256) ws[i] = W[i];
    __syncthreads();

    const float4* ag = (const float4*)g_agg + (size_t)blockIdx.x * 1024;
#pragma unroll
    for (int it = 0; it < 4; it++) {
        int i = tid + it * 256;
        int node = i >> 4, q = i & 15;
        float4 a = ag[i];
        float h0 = fmaxf(a.x * sc[4 * q + 0] + sh[4 * q + 0], 0.f);
        float h1 = fmaxf(a.y * sc[4 * q + 1] + sh[4 * q + 1], 0.f);
        float h2 = fmaxf(a.z * sc[4 * q + 2] + sh[4 * q + 2], 0.f);
        float h3 = fmaxf(a.w * sc[4 * q + 3] + sh[4 * q + 3], 0.f);
        float* hp = &hs[node * 65];
        hp[4 * q + 0] = h0; hp[4 * q + 1] = h1;
        hp[4 * q + 2] = h2; hp[4 * q + 3] = h3;
    }
    __syncthreads();

    int tx = tid & 15, ty = tid >> 4;
    float acc[4][4] = {};
#pragma unroll 16
    for (int k = 0; k < 64; k++) {
        float4 wv = *(const float4*)&ws[k * 64 + 4 * tx];
        float h0 = hs[(4 * ty + 0) * 65 + k];
        float h1 = hs[(4 * ty + 1) * 65 + k];
        float h2 = hs[(4 * ty + 2) * 65 + k];
        float h3 = hs[(4 * ty + 3) * 65 + k];
        acc[0][0] += h0 * wv.x; acc[0][1] += h0 * wv.y; acc[0][2] += h0 * wv.z; acc[0][3] += h0 * wv.w;
        acc[1][0] += h1 * wv.x; acc[1][1] += h1 * wv.y; acc[1][2] += h1 * wv.z; acc[1][3] += h1 * wv.w;
        acc[2][0] += h2 * wv.x; acc[2][1] += h2 * wv.y; acc[2][2] += h2 * wv.z; acc[2][3] += h2 * wv.w;
        acc[3][0] += h3 * wv.x; acc[3][1] += h3 * wv.y; acc[3][2] += h3 * wv.z; acc[3][3] += h3 * wv.w;
    }

    int node0 = blockIdx.x * 64 + 4 * ty;
#pragma unroll
    for (int i = 0; i < 4; i++) {
        float di = g_dinv[node0 + i];
        __half2 h0 = __floats2half2_rn(acc[i][0] * di, acc[i][1] * di);
        __half2 h1 = __floats2half2_rn(acc[i][2] * di, acc[i][3] * di);
        ((uint2*)&g_xwh[(size_t)(node0 + i) * 32])[tx] = make_uint2(h2_as_u(h0), h2_as_u(h1));
    }
}

// h2 = relu(v2*sc2+sh2) from fp16 v2 ; pool[batch[i]] += h2 ; cnt
__global__ void k_pool(const int* __restrict__ batch) {
    unsigned t = blockIdx.x * blockDim.x + threadIdx.x;
    unsigned i = t >> 4;
    unsigned j = t & 15u;
    int g = batch[i];
    uint2 u = ((const uint2*)g_aggh)[(size_t)i * 16 + j];
    __half2 a0 = *reinterpret_cast<__half2*>(&u.x);
    __half2 a1 = *reinterpret_cast<__half2*>(&u.y);
    float2 f0 = __half22float2(a0);
    float2 f1 = __half22float2(a1);
    float4 s4 = ((const float4*)g_scale2)[j];
    float4 h4 = ((const float4*)g_shift2)[j];
    float4 hh;
    hh.x = fmaxf(f0.x * s4.x + h4.x, 0.f);
    hh.y = fmaxf(f0.y * s4.y + h4.y, 0.f);
    hh.z = fmaxf(f1.x * s4.z + h4.z, 0.f);
    hh.w = fmaxf(f1.y * s4.w + h4.w, 0.f);
    red_add_v4(&g_pool[(size_t)g * HID + 4 * j], hh);
    if (j == 0) atomicAdd(&g_cnt[g], 1.0f);
}

__global__ void k_head(const float* __restrict__ gf,
                       const float* __restrict__ Wo1, const float* __restrict__ bo1,
                       const float* __restrict__ Wo2, const float* __restrict__ bo2,
                       const float* __restrict__ Wb1, const float* __restrict__ bb1,
                       const float* __restrict__ Wb2, const float* __restrict__ bb2,
                       float* __restrict__ out) {
    int g = blockIdx.x;
    int lane = threadIdx.x;
    __shared__ float c[HID + G_FEAT];
    float inv = 1.0f / fmaxf(g_cnt[g], 1.0f);
    for (int k = lane; k < HID; k += 32) c[k] = g_pool[(size_t)g * HID + k] * inv;
    if (lane < G_FEAT) c[HID + lane] = gf[(size_t)g * G_FEAT + lane];
    __syncwarp();

    float ho = bo1[lane];
#pragma unroll 8
    for (int k = 0; k < HID + G_FEAT; k++) ho += c[k] * Wo1[k * 32 + lane];
    ho = fmaxf(ho, 0.f) * Wo2[lane];
#pragma unroll
    for (int o = 16; o; o >>= 1) ho += __shfl_xor_sync(0xffffffffu, ho, o);
    if (lane == 0) out[g] = ho + bo2[0];

    float hb = bb1[lane];
#pragma unroll 8
    for (int k = 0; k < HID + G_FEAT; k++) hb += c[k] * Wb1[k * 32 + lane];
    hb = fmaxf(hb, 0.f) * Wb2[lane];
#pragma unroll
    for (int o = 16; o; o >>= 1) hb += __shfl_xor_sync(0xffffffffu, hb, o);
    if (lane == 0) out[NG + g] = hb + bb2[0];
}

// ---------------- launch --------------------------------------------------------
extern "C" void kernel_launch(void* const* d_in, const int* in_sizes, int n_in,
                              void* d_out, int out_size) {
    const float* x      = (const float*)d_in[0];
    const int*   ei     = (const int*)d_in[1];
    const int*   batch  = (const int*)d_in[2];
    const float* gf     = (const float*)d_in[3];
    const float* W1     = (const float*)d_in[4];
    const float* b1     = (const float*)d_in[5];
    const float* gamma1 = (const float*)d_in[6];
    const float* beta1  = (const float*)d_in[7];
    const float* W2     = (const float*)d_in[8];
    const float* b2     = (const float*)d_in[9];
    const float* gamma2 = (const float*)d_in[10];
    const float* beta2  = (const float*)d_in[11];
    const float* Wo1    = (const float*)d_in[12];
    const float* bo1    = (const float*)d_in[13];
    const float* Wo2    = (const float*)d_in[14];
    const float* bo2    = (const float*)d_in[15];
    const float* Wb1    = (const float*)d_in[16];
    const float* bb1    = (const float*)d_in[17];
    const float* Wb2    = (const float*)d_in[18];
    const float* bb2    = (const float*)d_in[19];
    float* out = (float*)d_out;

    const int* src = ei;
    const int* dst = ei + NE;

    void *p_deg, *p_ecnt, *p_ps1, *p_pq1, *p_ps2, *p_pq2, *p_pool, *p_cnt;
    void *p_scale1, *p_shift1, *p_scale2, *p_shift2;
    cudaGetSymbolAddress(&p_deg,  g_deg);
    cudaGetSymbolAddress(&p_ecnt, g_ecnt);
    cudaGetSymbolAddress(&p_ps1,  g_psum1);
    cudaGetSymbolAddress(&p_pq1,  g_pss1);
    cudaGetSymbolAddress(&p_ps2,  g_psum2);
    cudaGetSymbolAddress(&p_pq2,  g_pss2);
    cudaGetSymbolAddress(&p_pool, g_pool);
    cudaGetSymbolAddress(&p_cnt,  g_cnt);
    cudaGetSymbolAddress(&p_scale1, g_scale1);
    cudaGetSymbolAddress(&p_shift1, g_shift1);
    cudaGetSymbolAddress(&p_scale2, g_scale2);
    cudaGetSymbolAddress(&p_shift2, g_shift2);

    cudaMemsetAsync(p_deg,  0, sizeof(int) * NN);
    cudaMemsetAsync(p_ecnt, 0, sizeof(int));
    cudaMemsetAsync(p_ps1,  0, sizeof(float) * NSLOT * HID);
    cudaMemsetAsync(p_pq1,  0, sizeof(float) * NSLOT * HID);
    cudaMemsetAsync(p_ps2,  0, sizeof(float) * NSLOT * HID);
    cudaMemsetAsync(p_pq2,  0, sizeof(float) * NSLOT * HID);
    cudaMemsetAsync(p_pool, 0, sizeof(float) * NG * HID);
    cudaMemsetAsync(p_cnt,  0, sizeof(float) * NG);

    // ----- CSR build -----
    k_degree<<<NE / 256, 256>>>(dst);
    k_offsets<<<NN / 256, 256>>>();
    k_fill<<<NE / 256, 256>>>(src, dst);

    // ----- layer 1 -----
    k_gemm1<<<NN / 64, 256>>>(x, W1);
    k_gather<false><<<NN / 8, 256>>>(b1, (float*)p_ps1, (float*)p_pq1);
    k_bnstats<<<1, HID>>>((const float*)p_ps1, (const float*)p_pq1, gamma1, beta1,
                          (float*)p_scale1, (float*)p_shift1);

    // ----- layer 2 -----
    k_gemm2<<<NN / 64, 256>>>(W2);
    k_gather<true><<<NN / 8, 256>>>(b2, (float*)p_ps2, (float*)p_pq2);
    k_bnstats<<<1, HID>>>((const float*)p_ps2, (const float*)p_pq2, gamma2, beta2,
                          (float*)p_scale2, (float*)p_shift2);

    // ----- pool + heads -----
    k_pool<<<(NN * 16) / 256, 256>>>(batch);
    k_head<<<NG, 32>>>(gf, Wo1, bo1, Wo2, bo2, Wb1, bb1, Wb2, bb2, out);
}